// round 4
// baseline (speedup 1.0000x reference)
#include <cuda_runtime.h>
#include <cstdint>
#include <cstddef>

// Problem constants (fixed by the reference):
//   B=8, C=64, N=2000, T=12, E=64000, HID=32
// Algebra: out[b,e,c] = A[b,idx[e],c] + Bm[b,idy[e],c] + conv_b[c]
//   A  = (x . t_up ) @ M1 + conv_b,  M1 = W1_scale * (W3 @ conv_w[:, :32]^T)   (64x64)
//   Bm = (x . t_dn ) @ M2,           M2 = W2_scale * (W4 @ conv_w[:, 32:]^T)   (64x64)
// (conv_b folded into the A table so the edge kernel is a pure 2-gather add.)

namespace {
constexpr int Bc = 8;
constexpr int Cc = 64;
constexpr int Nc = 2000;
constexpr int Tc = 12;
constexpr int Ec = 64000;
constexpr int Hc = 32;
constexpr int TILE_N = 64;
}

// Device scratch (no allocation allowed in kernel_launch).
__device__ float g_M1[Cc * Cc];
__device__ float g_M2[Cc * Cc];
__device__ float g_A[(size_t)Bc * Nc * Cc];   // 4 MB
__device__ float g_Bm[(size_t)Bc * Nc * Cc];  // 4 MB

// ---------------------------------------------------------------------------
// Kernel 0: fold W1_scale*W3 @ conv_w[:, :32]^T and W2_scale*W4 @ conv_w[:, 32:]^T
// into two 64x64 matrices. Parallelized: 16 CTAs x 256 threads, ONE output
// element per thread (64 loads each, high MLP) so this prologue costs ~1-2 us
// instead of 6-8 us serialized on one SM.
// ---------------------------------------------------------------------------
__global__ void __launch_bounds__(256) prep_kernel(const float* __restrict__ w1s,
                                                   const float* __restrict__ w2s,
                                                   const float* __restrict__ W3,
                                                   const float* __restrict__ W4,
                                                   const float* __restrict__ conv_w) {
    const int o = blockIdx.x * 256 + threadIdx.x;   // 0..4095
    const int c  = o >> 6;   // input channel
    const int co = o & 63;   // output channel
    const float s1 = __ldg(w1s);
    const float s2 = __ldg(w2s);
    float a1 = 0.f, a2 = 0.f;
#pragma unroll
    for (int h = 0; h < Hc; ++h) {
        a1 = fmaf(__ldg(W3 + c * Hc + h), __ldg(conv_w + co * (2 * Hc) + h),      a1);
        a2 = fmaf(__ldg(W4 + c * Hc + h), __ldg(conv_w + co * (2 * Hc) + Hc + h), a2);
    }
    g_M1[o] = s1 * a1;
    g_M2[o] = s2 * a2;
}

// ---------------------------------------------------------------------------
// Kernel 1: per-node tables.
//   u[b,n,c] = sum_t x[b,c,n,t] * (t/11)
//   v[b,n,c] = sum_t x[b,c,n,t] * (1 - t/11)
//   A[b,n,co]  = sum_c u[c] * M1[c,co] + conv_b[co]
//   Bm[b,n,co] = sum_c v[c] * M2[c,co]
// One block = (b, tile of 64 n). 256 threads.
// Dynamic shared: m1(16KB) m2(16KB) u(16KB) v(16KB) = 64KB.
// ---------------------------------------------------------------------------
__global__ void __launch_bounds__(256) node_kernel(const float* __restrict__ x,
                                                   const float* __restrict__ conv_b) {
    extern __shared__ float sm[];
    float* m1  = sm;                  // [c][co] 64*64
    float* m2  = sm + 4096;
    float* u_s = sm + 8192;           // [c][n_local] 64*64
    float* v_s = sm + 12288;

    const int tid = threadIdx.x;

    // Stage M1/M2 into shared (vectorized).
    {
        const float4* M1g = reinterpret_cast<const float4*>(g_M1);
        const float4* M2g = reinterpret_cast<const float4*>(g_M2);
        float4* m1v = reinterpret_cast<float4*>(m1);
        float4* m2v = reinterpret_cast<float4*>(m2);
#pragma unroll
        for (int i = tid; i < 1024; i += 256) {
            m1v[i] = M1g[i];
            m2v[i] = M2g[i];
        }
    }

    const int b  = blockIdx.y;
    const int n0 = blockIdx.x * TILE_N;
    const int n_local = tid & 63;
    const int c0 = tid >> 6;          // 0..3
    const int n  = n0 + n_local;

    // Phase 1: time reduction. Each thread covers 16 (c, n_local) pairs.
    // x[b,c,n,0..11] is 48 contiguous bytes; row offset multiple of 48B -> 16B aligned.
#pragma unroll
    for (int c = c0; c < Cc; c += 4) {
        float u = 0.f, v = 0.f;
        if (n < Nc) {
            const float4* xp = reinterpret_cast<const float4*>(
                x + ((size_t)(b * Cc + c) * Nc + n) * Tc);
            const float4 a0 = xp[0];
            const float4 a1 = xp[1];
            const float4 a2 = xp[2];
            const float xv[12] = {a0.x, a0.y, a0.z, a0.w,
                                  a1.x, a1.y, a1.z, a1.w,
                                  a2.x, a2.y, a2.z, a2.w};
#pragma unroll
            for (int t = 0; t < Tc; ++t) {
                const float tu = (float)t * (1.0f / 11.0f);
                u = fmaf(xv[t], tu, u);
                v = fmaf(xv[t], 1.0f - tu, v);
            }
        }
        u_s[c * 64 + n_local] = u;   // [c][n] layout: consecutive n -> no bank conflict
        v_s[c * 64 + n_local] = v;
    }
    __syncthreads();

    // Phase 2: 64x64 per-tile matmul. Thread (c_out = tid&63, ng = tid>>6)
    // computes 16 n rows for its c_out. u_s read is warp-uniform (broadcast),
    // m1 read is consecutive c_out (conflict-free).
    const int c_out = tid & 63;
    const int ng    = tid >> 6;
    const float cb  = __ldg(conv_b + c_out);
#pragma unroll
    for (int k = 0; k < 16; ++k) {
        const int nl = ng * 16 + k;
        float aA = cb, aB = 0.f;
#pragma unroll
        for (int c = 0; c < Cc; ++c) {
            aA = fmaf(u_s[c * 64 + nl], m1[c * 64 + c_out], aA);
            aB = fmaf(v_s[c * 64 + nl], m2[c * 64 + c_out], aB);
        }
        const int nn = n0 + nl;
        if (nn < Nc) {
            g_A [((size_t)b * Nc + nn) * 64 + c_out] = aA;  // warp writes 128B
            g_Bm[((size_t)b * Nc + nn) * 64 + c_out] = aB;
        }
    }
}

// ---------------------------------------------------------------------------
// Kernel 2: edge gather + add. out[b,e,c] = A[b,idx[e],c] + Bm[b,idy[e],c]
// (conv_b already folded into A). 16 lanes per (b,e) row, float4 per lane:
// each gather is 256B = 2 full 128B lines, perfectly dense. Tables are
// L2-resident (8 MB). Output writes contiguous 4KB per block.
// ---------------------------------------------------------------------------
__global__ void __launch_bounds__(256) edge_kernel(const int* __restrict__ idx,
                                                   const int* __restrict__ idy,
                                                   float* __restrict__ out) {
    const int tid  = threadIdx.x;
    const int lane = tid & 15;
    const int row  = tid >> 4;            // 0..15
    const int e    = blockIdx.x * 16 + row;
    const int b    = blockIdx.y;

    const int n1 = __ldg(idx + e);
    const int n2 = __ldg(idy + e);

    const float4* ap = reinterpret_cast<const float4*>(g_A  + ((size_t)b * Nc + n1) * 64);
    const float4* bp = reinterpret_cast<const float4*>(g_Bm + ((size_t)b * Nc + n2) * 64);
    const float4  a  = ap[lane];
    const float4  r  = bp[lane];

    float4 o;
    o.x = a.x + r.x;
    o.y = a.y + r.y;
    o.z = a.z + r.z;
    o.w = a.w + r.w;

    reinterpret_cast<float4*>(out + ((size_t)b * Ec + e) * 64)[lane] = o;
}

// ---------------------------------------------------------------------------
extern "C" void kernel_launch(void* const* d_in, const int* in_sizes, int n_in,
                              void* d_out, int out_size) {
    const float* x      = (const float*)d_in[0];
    const int*   idx    = (const int*)  d_in[1];
    const int*   idy    = (const int*)  d_in[2];
    const float* w1s    = (const float*)d_in[3];
    const float* w2s    = (const float*)d_in[4];
    const float* W3     = (const float*)d_in[5];
    const float* W4     = (const float*)d_in[6];
    const float* conv_w = (const float*)d_in[7];
    const float* conv_b = (const float*)d_in[8];
    float*       out    = (float*)d_out;

    // 64 KB dynamic shared for node_kernel (above the 48 KB default).
    cudaFuncSetAttribute(node_kernel,
                         cudaFuncAttributeMaxDynamicSharedMemorySize, 64 * 1024);

    prep_kernel<<<16, 256>>>(w1s, w2s, W3, W4, conv_w);

    dim3 g1((Nc + TILE_N - 1) / TILE_N, Bc);     // 32 x 8 = 256 CTAs
    node_kernel<<<g1, 256, 64 * 1024>>>(x, conv_b);

    dim3 g2(Ec / 16, Bc);                         // 4000 x 8 CTAs
    edge_kernel<<<g2, 256>>>(idx, idy, out);
}

// round 6
// speedup vs baseline: 1.4694x; 1.4694x over previous
#include <cuda_runtime.h>
#include <cstdint>
#include <cstddef>

// Problem constants (fixed by the reference):
//   B=8, C=64, N=2000, T=12, E=64000, HID=32
// Algebra: out[b,e,c] = A[b,idx[e],c] + Bm[b,idy[e],c] + conv_b[c]
//   A  = s1 * (u @ W3) @ CW_L^T + conv_b,   u[b,n,c] = sum_t x[b,c,n,t] * (t/11)
//   Bm = s2 * (v @ W4) @ CW_R^T,            v[b,n,c] = sum_t x[b,c,n,t] * (1-t/11)
// The fold (W3 @ CW^T) is NOT precomputed (round-4 ncu: 12.2us latency-bound
// prep kernel). Chaining the two small GEMMs per tile has identical FLOPs
// (64x32x64 + 64x64x32 == 64x64x64) and removes a whole launch.

namespace {
constexpr int Bc = 8;
constexpr int Cc = 64;
constexpr int Nc = 2000;
constexpr int Tc = 12;
constexpr int Ec = 64000;
constexpr int Hc = 32;
constexpr int TILE_N = 64;

// Shared layout (floats), total 20480 floats = 80 KB:
constexpr int SM_U   = 0;      // u_s [c][nl]  64x64
constexpr int SM_V   = 4096;   // v_s [c][nl]  64x64
constexpr int SM_ZU  = 8192;   // z_u [h][nl]  32x64
constexpr int SM_ZV  = 10240;  // z_v [h][nl]  32x64
constexpr int SM_W3  = 12288;  // w3  [c][h]   64x32
constexpr int SM_W4  = 14336;  // w4  [c][h]   64x32
constexpr int SM_CWL = 16384;  // cwL [h][co]  32x64  (transposed conv_w left)
constexpr int SM_CWR = 18432;  // cwR [h][co]  32x64  (transposed conv_w right)
constexpr int SM_TOTAL_BYTES = 20480 * 4;
}

// Device scratch (no allocation allowed in kernel_launch).
__device__ float g_A[(size_t)Bc * Nc * Cc];   // 4 MB
__device__ float g_Bm[(size_t)Bc * Nc * Cc];  // 4 MB

// ---------------------------------------------------------------------------
// Node kernel: builds per-node tables A/Bm. One CTA = (b, 64-node tile),
// 256 threads, grid 32 x 8.
// ---------------------------------------------------------------------------
__global__ void __launch_bounds__(256) node_kernel(const float* __restrict__ x,
                                                   const float* __restrict__ W3,
                                                   const float* __restrict__ W4,
                                                   const float* __restrict__ conv_w,
                                                   const float* __restrict__ conv_b,
                                                   const float* __restrict__ w1s,
                                                   const float* __restrict__ w2s) {
    extern __shared__ float sm[];
    const int tid = threadIdx.x;
    const int b   = blockIdx.y;
    const int n0  = blockIdx.x * TILE_N;

    // ---- Stage weight LDGs EARLY (latency hidden under phase-1 x reads) ----
    // W3/W4: 512 float4 each -> 2 per thread (linear copy, layout kept [c][h]).
    // conv_w: 1024 float4 -> 4 per thread (transposed into cwL/cwR at STS time).
    float4 w3r[2], w4r[2], cwr[4];
#pragma unroll
    for (int k = 0; k < 2; ++k) {
        w3r[k] = reinterpret_cast<const float4*>(W3)[tid + k * 256];
        w4r[k] = reinterpret_cast<const float4*>(W4)[tid + k * 256];
    }
#pragma unroll
    for (int k = 0; k < 4; ++k)
        cwr[k] = reinterpret_cast<const float4*>(conv_w)[tid + k * 256];
    const float s1 = __ldg(w1s);
    const float s2 = __ldg(w2s);

    // ---- Phase 1: time reduction into u_s/v_s ([c][nl], conflict-free) ----
    const int n_local = tid & 63;
    const int c0      = tid >> 6;    // 0..3
    const int n       = n0 + n_local;
#pragma unroll
    for (int c = c0; c < Cc; c += 4) {
        float u = 0.f, v = 0.f;
        if (n < Nc) {
            const float4* xp = reinterpret_cast<const float4*>(
                x + ((size_t)(b * Cc + c) * Nc + n) * Tc);
            const float4 a0 = xp[0];
            const float4 a1 = xp[1];
            const float4 a2 = xp[2];
            const float xv[12] = {a0.x, a0.y, a0.z, a0.w,
                                  a1.x, a1.y, a1.z, a1.w,
                                  a2.x, a2.y, a2.z, a2.w};
#pragma unroll
            for (int t = 0; t < Tc; ++t) {
                const float tu = (float)t * (1.0f / 11.0f);
                u = fmaf(xv[t], tu, u);
                v = fmaf(xv[t], 1.0f - tu, v);
            }
        }
        sm[SM_U + c * 64 + n_local] = u;
        sm[SM_V + c * 64 + n_local] = v;
    }

    // ---- Commit staged weights to shared ----
#pragma unroll
    for (int k = 0; k < 2; ++k) {
        reinterpret_cast<float4*>(sm + SM_W3)[tid + k * 256] = w3r[k];
        reinterpret_cast<float4*>(sm + SM_W4)[tid + k * 256] = w4r[k];
    }
#pragma unroll
    for (int k = 0; k < 4; ++k) {
        const int f   = tid + k * 256;      // float4 index into conv_w [co][64]
        const int co  = f >> 4;             // 16 float4 per row
        const int hh4 = (f & 15) * 4;       // 0..60
        const float cv[4] = {cwr[k].x, cwr[k].y, cwr[k].z, cwr[k].w};
#pragma unroll
        for (int j = 0; j < 4; ++j) {
            const int hh = hh4 + j;
            if (hh < Hc) sm[SM_CWL + hh * 64 + co]        = cv[j];
            else         sm[SM_CWR + (hh - Hc) * 64 + co] = cv[j];
        }
    }
    __syncthreads();

    // ---- Phase 2a: z_u = u @ W3, z_v = v @ W4  (64n x 32h per tile) ----
    // Thread tile: 4 n x 2 h. Stored transposed: z[h][n].
    {
        const int n4 = (tid & 15) * 4;
        const int h2 = (tid >> 4) * 2;
        float au0x=0,au0y=0,au0z=0,au0w=0, au1x=0,au1y=0,au1z=0,au1w=0;
        float av0x=0,av0y=0,av0z=0,av0w=0, av1x=0,av1y=0,av1z=0,av1w=0;
#pragma unroll
        for (int c = 0; c < Cc; ++c) {
            const float4 u4 = *reinterpret_cast<const float4*>(sm + SM_U + c * 64 + n4);
            const float4 v4 = *reinterpret_cast<const float4*>(sm + SM_V + c * 64 + n4);
            const float w3a = sm[SM_W3 + c * Hc + h2];
            const float w3b = sm[SM_W3 + c * Hc + h2 + 1];
            const float w4a = sm[SM_W4 + c * Hc + h2];
            const float w4b = sm[SM_W4 + c * Hc + h2 + 1];
            au0x = fmaf(u4.x, w3a, au0x); au0y = fmaf(u4.y, w3a, au0y);
            au0z = fmaf(u4.z, w3a, au0z); au0w = fmaf(u4.w, w3a, au0w);
            au1x = fmaf(u4.x, w3b, au1x); au1y = fmaf(u4.y, w3b, au1y);
            au1z = fmaf(u4.z, w3b, au1z); au1w = fmaf(u4.w, w3b, au1w);
            av0x = fmaf(v4.x, w4a, av0x); av0y = fmaf(v4.y, w4a, av0y);
            av0z = fmaf(v4.z, w4a, av0z); av0w = fmaf(v4.w, w4a, av0w);
            av1x = fmaf(v4.x, w4b, av1x); av1y = fmaf(v4.y, w4b, av1y);
            av1z = fmaf(v4.z, w4b, av1z); av1w = fmaf(v4.w, w4b, av1w);
        }
        // Fold the scalar scales here (cheapest point).
        *reinterpret_cast<float4*>(sm + SM_ZU + h2 * 64 + n4)       = make_float4(s1*au0x, s1*au0y, s1*au0z, s1*au0w);
        *reinterpret_cast<float4*>(sm + SM_ZU + (h2 + 1) * 64 + n4) = make_float4(s1*au1x, s1*au1y, s1*au1z, s1*au1w);
        *reinterpret_cast<float4*>(sm + SM_ZV + h2 * 64 + n4)       = make_float4(s2*av0x, s2*av0y, s2*av0z, s2*av0w);
        *reinterpret_cast<float4*>(sm + SM_ZV + (h2 + 1) * 64 + n4) = make_float4(s2*av1x, s2*av1y, s2*av1z, s2*av1w);
    }
    __syncthreads();

    // ---- Phase 2b: A = z_u @ cwL^T (+bias), Bm = z_v @ cwR^T ----
    // Thread tile: 4 n x 4 co, both matrices. 32 FMA per h step.
    {
        const int co4 = (tid & 15) * 4;
        const int n4g = (tid >> 4) * 4;
        float accA[4][4] = {};
        float accB[4][4] = {};
#pragma unroll
        for (int h = 0; h < Hc; ++h) {
            const float4 zu = *reinterpret_cast<const float4*>(sm + SM_ZU + h * 64 + n4g);
            const float4 zv = *reinterpret_cast<const float4*>(sm + SM_ZV + h * 64 + n4g);
            const float4 cl = *reinterpret_cast<const float4*>(sm + SM_CWL + h * 64 + co4);
            const float4 cr = *reinterpret_cast<const float4*>(sm + SM_CWR + h * 64 + co4);
            const float zus[4] = {zu.x, zu.y, zu.z, zu.w};
            const float zvs[4] = {zv.x, zv.y, zv.z, zv.w};
            const float cls[4] = {cl.x, cl.y, cl.z, cl.w};
            const float crs[4] = {cr.x, cr.y, cr.z, cr.w};
#pragma unroll
            for (int i = 0; i < 4; ++i)
#pragma unroll
                for (int j = 0; j < 4; ++j) {
                    accA[i][j] = fmaf(zus[i], cls[j], accA[i][j]);
                    accB[i][j] = fmaf(zvs[i], crs[j], accB[i][j]);
                }
        }
        const float4 cb4 = *reinterpret_cast<const float4*>(conv_b + co4);
        const float cbs[4] = {cb4.x, cb4.y, cb4.z, cb4.w};
#pragma unroll
        for (int i = 0; i < 4; ++i) {
            const int nn = n0 + n4g + i;
            if (nn < Nc) {
                float4 oa, ob;
                oa.x = accA[i][0] + cbs[0]; oa.y = accA[i][1] + cbs[1];
                oa.z = accA[i][2] + cbs[2]; oa.w = accA[i][3] + cbs[3];
                ob.x = accB[i][0]; ob.y = accB[i][1];
                ob.z = accB[i][2]; ob.w = accB[i][3];
                reinterpret_cast<float4*>(g_A  + ((size_t)b * Nc + nn) * 64 + co4)[0] = oa;
                reinterpret_cast<float4*>(g_Bm + ((size_t)b * Nc + nn) * 64 + co4)[0] = ob;
            }
        }
    }
}

// ---------------------------------------------------------------------------
// Edge kernel: out[b,e,c] = A[b,idx[e],c] + Bm[b,idy[e],c]  (bias in A).
// 16 lanes per (b,e) row, float4 per lane; each gather = 2 dense 128B lines
// from the 8MB L2-resident tables. Output contiguous 4KB per block.
// ---------------------------------------------------------------------------
__global__ void __launch_bounds__(256) edge_kernel(const int* __restrict__ idx,
                                                   const int* __restrict__ idy,
                                                   float* __restrict__ out) {
    const int tid  = threadIdx.x;
    const int lane = tid & 15;
    const int row  = tid >> 4;            // 0..15
    const int e    = blockIdx.x * 16 + row;
    const int b    = blockIdx.y;

    const int n1 = __ldg(idx + e);
    const int n2 = __ldg(idy + e);

    const float4 a = reinterpret_cast<const float4*>(g_A  + ((size_t)b * Nc + n1) * 64)[lane];
    const float4 r = reinterpret_cast<const float4*>(g_Bm + ((size_t)b * Nc + n2) * 64)[lane];

    float4 o;
    o.x = a.x + r.x;
    o.y = a.y + r.y;
    o.z = a.z + r.z;
    o.w = a.w + r.w;

    reinterpret_cast<float4*>(out + ((size_t)b * Ec + e) * 64)[lane] = o;
}

// ---------------------------------------------------------------------------
extern "C" void kernel_launch(void* const* d_in, const int* in_sizes, int n_in,
                              void* d_out, int out_size) {
    const float* x      = (const float*)d_in[0];
    const int*   idx    = (const int*)  d_in[1];
    const int*   idy    = (const int*)  d_in[2];
    const float* w1s    = (const float*)d_in[3];
    const float* w2s    = (const float*)d_in[4];
    const float* W3     = (const float*)d_in[5];
    const float* W4     = (const float*)d_in[6];
    const float* conv_w = (const float*)d_in[7];
    const float* conv_b = (const float*)d_in[8];
    float*       out    = (float*)d_out;

    cudaFuncSetAttribute(node_kernel,
                         cudaFuncAttributeMaxDynamicSharedMemorySize, SM_TOTAL_BYTES);

    dim3 g1((Nc + TILE_N - 1) / TILE_N, Bc);     // 32 x 8 = 256 CTAs
    node_kernel<<<g1, 256, SM_TOTAL_BYTES>>>(x, W3, W4, conv_w, conv_b, w1s, w2s);

    dim3 g2(Ec / 16, Bc);                         // 4000 x 8 CTAs
    edge_kernel<<<g2, 256>>>(idx, idy, out);
}